// round 10
// baseline (speedup 1.0000x reference)
#include <cuda_runtime.h>
#include <math.h>

// BoundaryLoss collapses analytically:
//   dist_map = min(dist_to_zero_set, dist_to_nonzero_set) == 0 everywhere
//   => final_weight = 1 + THETA = 6 (constant)
//   => out = 6 * mean( softplus(pred) - pred*target ),  N = 524288
//
// Grid 128 x 1024 (uniform single wave). Fence-free single-node finish:
// each block atomicAdds (scaled_partial + 2^32) into one double; the arrival
// count rides the high bits of the same word, so the block seeing
// old >= 127*2^32 is provably last without any __threadfence.
// Tail-shaved finish: partials are pre-scaled by 6/N (last block does just a
// subtract + store), and the re-arm is a plain store (stream order between
// graph replays publishes it before the next replay's first atomic; the
// tag count proves no other block of THIS replay will touch g_accum).

#define N_ELEMS   524288
#define BLOCKS    128
#define THREADS   1024       // BLOCKS*THREADS == N_ELEMS/4 exactly

#define TAG       4294967296.0                    // 2^32 per-block arrival tag
#define LAST_THR  (127.0 * 4294967296.0)
#define FULL_TAG  (128.0 * 4294967296.0)
#define SCALE     (6.0f / (float)N_ELEMS)

__device__ double g_accum = 0.0;

__global__ __launch_bounds__(THREADS) void bce_atomic_kernel(
    const float* __restrict__ pred, const float* __restrict__ target,
    float* __restrict__ out)
{
    __shared__ float warp_sums[THREADS / 32];

    const int gid = blockIdx.x * THREADS + threadIdx.x;

    const float4 p = reinterpret_cast<const float4*>(pred)[gid];
    const float4 t = reinterpret_cast<const float4*>(target)[gid];

    // Linear part: max(x,0) - x*t
    float lin = (fmaxf(p.x, 0.0f) - p.x * t.x)
              + (fmaxf(p.y, 0.0f) - p.y * t.y)
              + (fmaxf(p.z, 0.0f) - p.z * t.z)
              + (fmaxf(p.w, 0.0f) - p.w * t.w);

    // Transcendental part with log-fusion:
    // sum log(1+e^-|x|) = log(prod (1+e^-|x|)); per-thread product <= 2^4,
    // pair-fused across lanes <= 2^8 (fp32-safe).
    float e0 = __expf(-fabsf(p.x));
    float e1 = __expf(-fabsf(p.y));
    float e2 = __expf(-fabsf(p.z));
    float e3 = __expf(-fabsf(p.w));
    float pr = ((1.0f + e0) * (1.0f + e1)) * ((1.0f + e2) * (1.0f + e3));

    float pr_nb = __shfl_down_sync(0xFFFFFFFFu, pr, 1);
    float s = lin;
    if ((threadIdx.x & 1) == 0)
        s += __logf(pr * pr_nb);

    // warp reduce
    #pragma unroll
    for (int off = 16; off > 0; off >>= 1)
        s += __shfl_down_sync(0xFFFFFFFFu, s, off);

    const int lane = threadIdx.x & 31;
    const int wid  = threadIdx.x >> 5;
    if (lane == 0) warp_sums[wid] = s;
    __syncthreads();

    if (wid == 0) {
        float v = (lane < THREADS / 32) ? warp_sums[lane] : 0.0f;
        #pragma unroll
        for (int off = 16; off > 0; off >>= 1)
            v += __shfl_down_sync(0xFFFFFFFFu, v, off);

        if (lane == 0) {
            // Pre-scaled partial: last block finishes with subtract + store.
            double contrib = (double)(v * SCALE) + TAG;
            double old = atomicAdd(&g_accum, contrib);
            if (old >= LAST_THR) {
                // Provably last: all 128 partials are in this very word.
                out[0] = (float)((old + contrib) - FULL_TAG);
                g_accum = 0.0;   // plain-store re-arm (no ATOMG on the tail)
            }
        }
    }
}

extern "C" void kernel_launch(void* const* d_in, const int* in_sizes, int n_in,
                              void* d_out, int out_size)
{
    const float* pred   = (const float*)d_in[0];
    const float* target = (const float*)d_in[1];
    float* out = (float*)d_out;

    bce_atomic_kernel<<<BLOCKS, THREADS>>>(pred, target, out);
}